// round 11
// baseline (speedup 1.0000x reference)
#include <cuda_runtime.h>
#include <cuda_fp16.h>
#include <cstdint>

// ---------------- problem constants ----------------
#define Nn 10000
#define Ee 160000
#define Tt 32
#define Hh 256
#define NFd 192
#define TTEACH 24
#define MST 320            // macc row stride (256 msg + 6 inputs + pad)

// edge-GEMM tiling: 2 sub-tiles of 64 edges share one B chunk
#define EM 128             // edges per CTA (2 x 64)
#define EN 256
#define EK 768
#define ECH 64
#define NCHUNK (EK/ECH)

// edge SMEM: A[2 buf][2 sub] 8KB each = 32KB; B[2 buf] 32KB = 64KB; total 96KB
// epilogue scratch 64x258 fp32 = 66KB reuses the region after the loop.
#define SM_B_BASE 32768
#define SM_EDGE_TOTAL 98304
#define TSTRIDE 258

// node GEMM smem
#define GM_A0 0
#define GM_A1 16384
#define GM_B0 32768
#define GM_B1 40960
#define SM_GEMM_TOTAL 49152

// ---------------- device scratch ----------------
static __device__ float  g_h[Nn * Hh];
static __device__ __half g_fh16[Nn * NFd];
static __device__ __half g_AB16[Nn * 1536];
static __device__ float  g_macc[Nn * MST];
static __device__ float  g_mbase[Nn * Hh];
static __device__ float  g_invcnt[Nn];
static __device__ float  g_cntf[Nn];
static __device__ float  g_zsum[Nn * 3];
static __device__ float  g_in6[Nn * 6];
static __device__ int    g_deg[Nn];
static __device__ int    g_base[Nn + 1];
static __device__ int    g_cur[Nn];
static __device__ int    g_src[Ee];
static __device__ int    g_dst[Ee];
static __device__ int    g_srcs[Ee];
static __device__ int    g_dsts[Ee];
static __device__ float  g_zs[3 * Ee];
static __device__ int    g_is32;
// weight staging + fp16 packs
static __device__ float  g_W1ab[192 * 1536];
static __device__ float  g_biasab[1536];
static __device__ float  g_WfXF[256 * 256];
static __device__ float  g_biasWfX[256];
static __device__ float  g_WhxF[320 * 1024];
static __device__ float  g_biasWhx[1024];
static __device__ __half g_WfX16[256 * 256];
static __device__ __half g_W1ab16[192 * 1536];
static __device__ __half g_Whx16[320 * 1024];
static __device__ __half g_W2h[NCHUNK * EN * ECH];

// ---------------- helpers ----------------
__device__ __forceinline__ uint32_t smem_u32(const void* p) {
    uint32_t a;
    asm("{ .reg .u64 t; cvta.to.shared.u64 t, %1; cvt.u32.u64 %0, t; }" : "=r"(a) : "l"(p));
    return a;
}
#define SWZ128(off) ((off) ^ (((off) >> 3) & 0x70))

__device__ __forceinline__ void ldm4(uint32_t* r, uint32_t addr) {
    asm volatile("ldmatrix.sync.aligned.m8n8.x4.shared.b16 {%0,%1,%2,%3}, [%4];"
                 : "=r"(r[0]), "=r"(r[1]), "=r"(r[2]), "=r"(r[3]) : "r"(addr));
}
__device__ __forceinline__ void ldm2(uint32_t* r, uint32_t addr) {
    asm volatile("ldmatrix.sync.aligned.m8n8.x2.shared.b16 {%0,%1}, [%2];"
                 : "=r"(r[0]), "=r"(r[1]) : "r"(addr));
}
__device__ __forceinline__ void mma_f16(float* c, const uint32_t* a, const uint32_t* b) {
    asm volatile(
        "mma.sync.aligned.m16n8k16.row.col.f32.f16.f16.f32 "
        "{%0,%1,%2,%3}, {%4,%5,%6,%7}, {%8,%9}, {%0,%1,%2,%3};"
        : "+f"(c[0]), "+f"(c[1]), "+f"(c[2]), "+f"(c[3])
        : "r"(a[0]), "r"(a[1]), "r"(a[2]), "r"(a[3]), "r"(b[0]), "r"(b[1]));
}
__device__ __forceinline__ void cpasync16(uint32_t smem_addr, const void* gptr) {
    asm volatile("cp.async.cg.shared.global [%0], [%1], 16;"
                 :: "r"(smem_addr), "l"(gptr) : "memory");
}
#define CP_COMMIT() asm volatile("cp.async.commit_group;" ::: "memory")
#define CP_WAIT0()  asm volatile("cp.async.wait_group 0;" ::: "memory")

// ---------------- setup kernels ----------------
__global__ void k_init() {
    int i = blockIdx.x * blockDim.x + threadIdx.x;
    int st = gridDim.x * blockDim.x;
    for (int j = i; j < Nn * Hh; j += st) g_h[j] = 0.f;
    for (int j = i; j < Nn * 6; j += st) g_in6[j] = 0.f;
    for (int j = i; j < Nn; j += st) g_deg[j] = 0;
    for (int j = i; j < Nn * 3; j += st) g_zsum[j] = 0.f;
    if (i == 0) g_is32 = 0;
}

__global__ void k_detect(const int* __restrict__ w) {
    int i = blockIdx.x * blockDim.x + threadIdx.x;
    int st = gridDim.x * blockDim.x;
    for (int j = i; j < 2 * Ee; j += st) {
        if ((j & 1) && w[j] != 0) g_is32 = 1;
    }
}

__global__ void k_extract(const void* __restrict__ eiraw) {
    int e = blockIdx.x * blockDim.x + threadIdx.x;
    if (e >= Ee) return;
    if (g_is32) {
        const int* p = (const int*)eiraw;
        g_src[e] = p[e];
        g_dst[e] = p[Ee + e];
    } else {
        const long long* p = (const long long*)eiraw;
        g_src[e] = (int)p[e];
        g_dst[e] = (int)p[Ee + e];
    }
}

__global__ void k_hist() {
    int e = blockIdx.x * blockDim.x + threadIdx.x;
    if (e < Ee) atomicAdd(&g_deg[g_dst[e]], 1);
}

__global__ void k_cnt() {
    int n = blockIdx.x * blockDim.x + threadIdx.x;
    if (n < Nn) {
        float c = fmaxf((float)g_deg[n], 1.f);
        g_cntf[n] = c;
        g_invcnt[n] = 1.f / c;
    }
}

__global__ void k_scan() {
    __shared__ int part[512];
    const int tid = threadIdx.x;
    const int per = (Nn + 511) / 512;
    int start = tid * per;
    int s = 0;
    for (int j = 0; j < per; j++) {
        int idx = start + j;
        if (idx < Nn) s += g_deg[idx];
    }
    part[tid] = s;
    __syncthreads();
    if (tid == 0) {
        int acc = 0;
        for (int i = 0; i < 512; i++) { int v = part[i]; part[i] = acc; acc += v; }
    }
    __syncthreads();
    int acc = part[tid];
    for (int j = 0; j < per; j++) {
        int idx = start + j;
        if (idx < Nn) { g_base[idx] = acc; g_cur[idx] = acc; acc += g_deg[idx]; }
    }
    if (tid == 511) g_base[Nn] = acc;
}

__global__ void k_place(const float* __restrict__ z) {
    int e = blockIdx.x * blockDim.x + threadIdx.x;
    if (e >= Ee) return;
    int d = g_dst[e];
    int pos = atomicAdd(&g_cur[d], 1);
    g_srcs[pos] = g_src[e];
    g_dsts[pos] = d;
    float z1 = z[(size_t)e * 4 + 1];
    float z2 = z[(size_t)e * 4 + 2];
    float z3 = z[(size_t)e * 4 + 3];
    g_zs[pos] = z1;
    g_zs[Ee + pos] = z2;
    g_zs[2 * Ee + pos] = z3;
    atomicAdd(&g_zsum[d * 3 + 0], z1);
    atomicAdd(&g_zsum[d * 3 + 1], z2);
    atomicAdd(&g_zsum[d * 3 + 2], z3);
}

__global__ void k_b2base(const float* __restrict__ b2) {
    int idx = blockIdx.x * blockDim.x + threadIdx.x;
    if (idx >= Nn * MST) return;
    int n = idx / MST, c = idx % MST;
    if (c < 256) {
        float v = g_zsum[n * 3 + 0] * b2[c]
                + g_zsum[n * 3 + 1] * b2[256 + c]
                + g_zsum[n * 3 + 2] * b2[512 + c];
        g_mbase[n * 256 + c] = v;
        g_macc[idx] = v;
    } else {
        g_macc[idx] = 0.f;
    }
}

__global__ void k_pack_w1(const float* __restrict__ W1, const float* __restrict__ b1) {
    int idx = blockIdx.x * blockDim.x + threadIdx.x;
    if (idx < 192 * 1536) {
        int row = idx / 1536, c = idx % 1536;
        float v;
        if (c < 768) {
            int k = c >> 8, j = c & 255;
            v = W1[k * 98304 + row * 256 + j];
        } else {
            int c2 = c - 768;
            int k = c2 >> 8, j = c2 & 255;
            v = W1[k * 98304 + (row + 192) * 256 + j];
        }
        g_W1ab[idx] = v;
    }
    if (idx < 1536) g_biasab[idx] = (idx < 768) ? b1[idx] : 0.f;
}

__global__ void k_build_wfx(const float* __restrict__ Wf, const float* __restrict__ Wo,
                            const float* __restrict__ bf, const float* __restrict__ bo) {
    int idx = blockIdx.x * blockDim.x + threadIdx.x;
    if (idx >= 256 * 256) return;
    int k = idx >> 8, n = idx & 255;
    float v = 0.f;
    if (n < 192) v = Wf[k * 192 + n];
    else if (n < 198) v = Wo[k * 6 + (n - 192)];
    g_WfXF[idx] = v;
    if (idx < 256) {
        float b = 0.f;
        if (idx < 192) b = bf[idx];
        else if (idx < 198) b = bo[idx - 192];
        g_biasWfX[idx] = b;
    }
}

__global__ void k_build_whx(const float* __restrict__ Whh, const float* __restrict__ Wih,
                            const float* __restrict__ bhh, const float* __restrict__ bih) {
    int idx = blockIdx.x * blockDim.x + threadIdx.x;
    if (idx >= 320 * 1024) return;
    int k = idx >> 10, j = idx & 1023;
    int g = j >> 6, rem = j & 63, gate = rem >> 4;
    int ii = (g << 4) + (rem & 15);
    float v = 0.f;
    if (k < 256) {
        if (gate == 0) v = Whh[ii * 256 + k];
        else if (gate == 1) v = Whh[(256 + ii) * 256 + k];
        else if (gate == 2) v = Whh[(512 + ii) * 256 + k];
    } else if (k < 262) {
        int q = k - 256;
        if (gate == 0) v = Wih[ii * 6 + q];
        else if (gate == 1) v = Wih[(256 + ii) * 6 + q];
        else if (gate == 3) v = Wih[(512 + ii) * 6 + q];
    }
    g_WhxF[idx] = v;
    if (idx < 1024) {
        int gg = idx >> 6, rr = idx & 63, gt = rr >> 4;
        int i2 = (gg << 4) + (rr & 15);
        float b;
        if (gt == 0) b = bhh[i2] + bih[i2];
        else if (gt == 1) b = bhh[256 + i2] + bih[256 + i2];
        else if (gt == 2) b = bhh[512 + i2];
        else b = bih[512 + i2];
        g_biasWhx[idx] = b;
    }
}

__global__ void k_pack_b16(const float* __restrict__ src, __half* __restrict__ dst,
                           int Kd, int Nd) {
    int idx = blockIdx.x * blockDim.x + threadIdx.x;
    if (idx >= Kd * Nd) return;
    int k = idx / Nd, n = idx % Nd;
    int kc = k >> 6, kk = k & 63, nb = n >> 6, nn = n & 63;
    int tile = kc * (Nd >> 6) + nb;
    uint32_t off = SWZ128((uint32_t)(nn * 128 + kk * 2));
    dst[(size_t)tile * 4096 + off / 2] = __float2half_rn(src[idx]);
}

__global__ void k_pack_w2(const float* __restrict__ W2) {
    int idx = blockIdx.x * blockDim.x + threadIdx.x;
    if (idx >= NCHUNK * EN * ECH) return;
    int chunk = idx / (EN * ECH);
    int rem = idx % (EN * ECH);
    int n = rem / ECH, k = rem % ECH;
    float w = W2[(size_t)(chunk * ECH + k) * 256 + n];
    uint32_t off = SWZ128((uint32_t)(n * 128 + k * 2));
    g_W2h[(size_t)chunk * (EN * ECH) + off / 2] = __float2half_rn(w);
}

// ---------------- unified fp16 tensor-core GEMM (pipelined, fused epilogues) ----
__global__ void __launch_bounds__(256) k_gemm16(
    const void* __restrict__ A, const __half* __restrict__ Bpk,
    const float* __restrict__ bias, void* __restrict__ C,
    int M, int Kd, int Nd, const float* __restrict__ rowscale,
    int relu, int a_fp16, int mode, int c_stride,
    int t, const float* __restrict__ x, float* __restrict__ out)
{
    extern __shared__ char gsm[];
    const uint32_t smem_base = smem_u32(gsm);

    const int tid = threadIdx.x;
    const int wid = tid >> 5;
    const int lane = tid & 31;
    const int m0 = blockIdx.x * 128;
    const int nblk = blockIdx.y;
    const int n0 = nblk * 64;
    const int nblocks = Nd >> 6;
    const int niter = Kd >> 6;

    const int m0w = (wid >> 1) * 32;
    const int n0w = (wid & 1) * 32;

    float c[2][4][4];
#pragma unroll
    for (int mi = 0; mi < 2; mi++)
#pragma unroll
        for (int ni = 0; ni < 4; ni++)
#pragma unroll
            for (int r = 0; r < 4; r++) c[mi][ni][r] = 0.f;

    const int arow = tid >> 1;
    const int acol0 = (tid & 1) * 32;
    const int am = m0 + arow;
    const bool av = am < M;
    float rs = 1.f;
    if (rowscale && av) rs = rowscale[am];
    const uint32_t a_sw[4] = {
        SWZ128((uint32_t)(arow * 128 + acol0 * 2)),
        SWZ128((uint32_t)(arow * 128 + (acol0 + 8) * 2)),
        SWZ128((uint32_t)(arow * 128 + (acol0 + 16) * 2)),
        SWZ128((uint32_t)(arow * 128 + (acol0 + 24) * 2))
    };

    const int a_r = lane & 15;
    const uint32_t a_kb = (uint32_t)((lane >> 4) << 4);
    const int b_r = lane & 7;
    const uint32_t b_kb = (uint32_t)(((lane >> 3) & 1) << 4);

    const uint32_t aoff[2] = {GM_A0, GM_A1};
    const uint32_t boff[2] = {GM_B0, GM_B1};

    auto stageA = [&](int kt, int bi) {
        if (a_fp16) {
            const __half* Ah = (const __half*)A + (size_t)am * Kd + kt;
#pragma unroll
            for (int i = 0; i < 4; i++) {
                uint4 v = make_uint4(0u, 0u, 0u, 0u);
                if (av) v = *(const uint4*)(Ah + acol0 + i * 8);
                *(uint4*)(gsm + aoff[bi] + a_sw[i]) = v;
            }
        } else {
            const float* Af = (const float*)A + (size_t)am * Kd + kt;
#pragma unroll
            for (int i = 0; i < 4; i++) {
                uint4 v = make_uint4(0u, 0u, 0u, 0u);
                if (av) {
                    float4 f0 = *(const float4*)(Af + acol0 + i * 8);
                    float4 f1 = *(const float4*)(Af + acol0 + i * 8 + 4);
                    __half2 h0 = __floats2half2_rn(f0.x * rs, f0.y * rs);
                    __half2 h1 = __floats2half2_rn(f0.z * rs, f0.w * rs);
                    __half2 h2 = __floats2half2_rn(f1.x * rs, f1.y * rs);
                    __half2 h3 = __floats2half2_rn(f1.z * rs, f1.w * rs);
                    v.x = *(uint32_t*)&h0; v.y = *(uint32_t*)&h1;
                    v.z = *(uint32_t*)&h2; v.w = *(uint32_t*)&h3;
                }
                *(uint4*)(gsm + aoff[bi] + a_sw[i]) = v;
            }
        }
    };
    auto issueB = [&](int kt, int bi) {
        const char* gB = (const char*)(Bpk + (size_t)((kt >> 6) * nblocks + nblk) * 4096);
        int j0 = tid * 16;
        cpasync16(smem_base + boff[bi] + (uint32_t)j0, gB + j0);
        cpasync16(smem_base + boff[bi] + (uint32_t)(j0 + 4096), gB + j0 + 4096);
        CP_COMMIT();
    };

    issueB(0, 0);
    stageA(0, 0);
    CP_WAIT0();
    __syncthreads();

    for (int it = 0; it < niter; it++) {
        const int cur = it & 1;
        const int nxt = cur ^ 1;
        if (it + 1 < niter) issueB((it + 1) << 6, nxt);

#pragma unroll
        for (int ks = 0; ks < 4; ks++) {
            uint32_t a[2][4];
#pragma unroll
            for (int mi = 0; mi < 2; mi++) {
                uint32_t row = (uint32_t)(m0w + mi * 16 + a_r);
                ldm4(a[mi], smem_base + aoff[cur] + SWZ128(row * 128 + (uint32_t)(ks * 32) + a_kb));
            }
#pragma unroll
            for (int ni = 0; ni < 4; ni++) {
                uint32_t nrow = (uint32_t)(n0w + ni * 8 + b_r);
                uint32_t b[2];
                ldm2(b, smem_base + boff[cur] + SWZ128(nrow * 128 + (uint32_t)(ks * 32) + b_kb));
                mma_f16(c[0][ni], a[0], b);
                mma_f16(c[1][ni], a[1], b);
            }
        }

        if (it + 1 < niter) {
            stageA((it + 1) << 6, nxt);
            CP_WAIT0();
        }
        __syncthreads();
    }

    if (mode == 2) {
        float* tile = (float*)gsm;   // 128 x 68
#pragma unroll
        for (int mi = 0; mi < 2; mi++) {
            int lr0 = m0w + mi * 16 + (lane >> 2);
            int lr1 = lr0 + 8;
#pragma unroll
            for (int ni = 0; ni < 4; ni++) {
                int col = n0w + ni * 8 + 2 * (lane & 3);
                float bv0 = bias[n0 + col], bv1 = bias[n0 + col + 1];
                float* cc = c[mi][ni];
                tile[lr0 * 68 + col] = cc[0] + bv0;
                tile[lr0 * 68 + col + 1] = cc[1] + bv1;
                tile[lr1 * 68 + col] = cc[2] + bv0;
                tile[lr1 * 68 + col + 1] = cc[3] + bv1;
            }
        }
        __syncthreads();
#pragma unroll
        for (int u = 0; u < 8; u++) {
            int unit = tid + u * 256;
            int row = unit >> 4, iloc = unit & 15;
            int gn = m0 + row;
            if (gn < M) {
                float gr  = tile[row * 68 + iloc];
                float gz  = tile[row * 68 + 16 + iloc];
                float gnh = tile[row * 68 + 32 + iloc];
                float gnx = tile[row * 68 + 48 + iloc];
                int hcol = nblk * 16 + iloc;
                float ic = rowscale[gn];
                float m = g_macc[(size_t)gn * MST + hcol] * ic;
                float r  = 1.f / (1.f + __expf(-gr));
                float zg = 1.f / (1.f + __expf(-gz));
                float arg = gnx + r * gnh;
                float nn = 1.f - 2.f / (__expf(2.f * arg) + 1.f);
                g_h[(size_t)gn * 256 + hcol] = (1.f - zg) * nn + zg * m;
            }
        }
        return;
    }

#pragma unroll
    for (int mi = 0; mi < 2; mi++) {
        int r0 = m0 + m0w + mi * 16 + (lane >> 2);
        int r1 = r0 + 8;
#pragma unroll
        for (int ni = 0; ni < 4; ni++) {
            int col = n0 + n0w + ni * 8 + 2 * (lane & 3);
            float bv0 = bias[col], bv1 = bias[col + 1];
            float* cc = c[mi][ni];
            float o00 = cc[0] + bv0, o01 = cc[1] + bv1;
            float o10 = cc[2] + bv0, o11 = cc[3] + bv1;
            if (relu) {
                o00 = fmaxf(o00, 0.f); o01 = fmaxf(o01, 0.f);
                o10 = fmaxf(o10, 0.f); o11 = fmaxf(o11, 0.f);
            }
            if (mode == 1) {
                if (r0 < M)
                    *(float2*)(g_macc + (size_t)r0 * MST + col) =
                        *(const float2*)(g_mbase + (size_t)r0 * 256 + col);
                if (r1 < M)
                    *(float2*)(g_macc + (size_t)r1 * MST + col) =
                        *(const float2*)(g_mbase + (size_t)r1 * 256 + col);
                if (col < 192) {
                    __half* Ch = (__half*)C;
                    if (r0 < M) {
                        __half2 h = __floats2half2_rn(o00, o01);
                        *(__half2*)(Ch + (size_t)r0 * c_stride + col) = h;
                    }
                    if (r1 < M) {
                        __half2 h = __floats2half2_rn(o10, o11);
                        *(__half2*)(Ch + (size_t)r1 * c_stride + col) = h;
                    }
                } else if (col < 198) {
                    int q = col - 192;
#pragma unroll
                    for (int half = 0; half < 2; half++) {
                        int rr = half ? r1 : r0;
                        float v0 = half ? o10 : o00;
                        float v1 = half ? o11 : o01;
                        if (rr < M) {
                            float mu0 = g_in6[rr * 6 + q] + v0;
                            float mu1 = g_in6[rr * 6 + q + 1] + v1;
                            if (t > 0) {
                                out[(size_t)rr * NFd + (t - 1) * 6 + q] = mu0;
                                out[(size_t)rr * NFd + (t - 1) * 6 + q + 1] = mu1;
                            }
                            float i0 = (t < TTEACH) ? x[(size_t)rr * NFd + t * 6 + q] : mu0;
                            float i1 = (t < TTEACH) ? x[(size_t)rr * NFd + t * 6 + q + 1] : mu1;
                            g_in6[rr * 6 + q] = i0;
                            g_in6[rr * 6 + q + 1] = i1;
                            float cf = g_cntf[rr];
                            g_macc[(size_t)rr * MST + 256 + q] = i0 * cf;
                            g_macc[(size_t)rr * MST + 256 + q + 1] = i1 * cf;
                        }
                    }
                }
            } else {
                __half* Ch = (__half*)C;
                if (r0 < M) {
                    __half2 h = __floats2half2_rn(o00, o01);
                    *(__half2*)(Ch + (size_t)r0 * c_stride + col) = h;
                }
                if (r1 < M) {
                    __half2 h = __floats2half2_rn(o10, o11);
                    *(__half2*)(Ch + (size_t)r1 * c_stride + col) = h;
                }
            }
        }
    }
}

// ---------------- edge GEMM: 2x64 sub-tiles share one B chunk, 512 threads ----
__global__ void __launch_bounds__(512, 1)
k_edge_mma()
{
    extern __shared__ char dsm[];
    __shared__ int sdst[EM];
    __shared__ float sz[3][EM];

    const uint32_t smem_base = smem_u32(dsm);
    const int tid = threadIdx.x;
    const int wid = tid >> 5;
    const int lane = tid & 31;
    const int e0 = blockIdx.x * EM;

    if (tid < EM) {
        sdst[tid] = g_dsts[e0 + tid];
        sz[0][tid] = g_zs[e0 + tid];
        sz[1][tid] = g_zs[Ee + e0 + tid];
        sz[2][tid] = g_zs[2 * Ee + e0 + tid];
    }
    __syncthreads();

    const int wsub = wid >> 3;          // warp's sub-tile (0/1)
    const int n0w = (wid & 7) * 32;     // warp's 32 cols

    float c[4][4][4];
#pragma unroll
    for (int mi = 0; mi < 4; mi++)
#pragma unroll
        for (int ni = 0; ni < 4; ni++)
#pragma unroll
            for (int r = 0; r < 4; r++) c[mi][ni][r] = 0.f;

    // A build: 4 threads per edge row (128 rows x 4 = 512 threads)
    const int grow = tid >> 2;              // global row in [0,128)
    const int asub = grow >> 6;             // sub-tile of this builder thread
    const int lrow = grow & 63;             // row within sub-tile
    const int acol0 = (tid & 3) * 16;
    const int srow = g_srcs[e0 + grow];
    const __half* pd = g_AB16 + (size_t)sdst[grow] * 1536;
    const __half* ps = g_AB16 + (size_t)srow * 1536 + 768;
    const uint32_t a_sub_off = (uint32_t)(asub * 8192);
    const uint32_t a_sw0 = SWZ128((uint32_t)(lrow * 128 + acol0 * 2));
    const uint32_t a_sw1 = SWZ128((uint32_t)(lrow * 128 + (acol0 + 8) * 2));

    const int a_r = lane & 15;
    const uint32_t a_kb = (uint32_t)((lane >> 4) << 4);
    const int b4_row = (lane & 7) + ((lane >> 4) << 3);
    const uint32_t b4_kb = (uint32_t)(((lane >> 3) & 1) << 4);

    const __half2 hzero = __float2half2_rn(0.f);
    const uint32_t aoff[2] = {0u, 16384u};          // A buffer base (per buf)
    const uint32_t boff[2] = {SM_B_BASE, SM_B_BASE + 32768u};

    uint4 ra0, ra1, rb0, rb1;

    auto convStoreA = [&](int chunk, int bi) {
        __half2 zh = __float2half2_rn(sz[chunk >> 2][grow]);
        __half2 r0 = __hmax2(__hmul2(__hadd2(*(__half2*)&ra0.x, *(__half2*)&rb0.x), zh), hzero);
        __half2 r1 = __hmax2(__hmul2(__hadd2(*(__half2*)&ra0.y, *(__half2*)&rb0.y), zh), hzero);
        __half2 r2 = __hmax2(__hmul2(__hadd2(*(__half2*)&ra0.z, *(__half2*)&rb0.z), zh), hzero);
        __half2 r3 = __hmax2(__hmul2(__hadd2(*(__half2*)&ra0.w, *(__half2*)&rb0.w), zh), hzero);
        uint4 v;
        v.x = *(uint32_t*)&r0; v.y = *(uint32_t*)&r1;
        v.z = *(uint32_t*)&r2; v.w = *(uint32_t*)&r3;
        *(uint4*)(dsm + aoff[bi] + a_sub_off + a_sw0) = v;
        r0 = __hmax2(__hmul2(__hadd2(*(__half2*)&ra1.x, *(__half2*)&rb1.x), zh), hzero);
        r1 = __hmax2(__hmul2(__hadd2(*(__half2*)&ra1.y, *(__half2*)&rb1.y), zh), hzero);
        r2 = __hmax2(__hmul2(__hadd2(*(__half2*)&ra1.z, *(__half2*)&rb1.z), zh), hzero);
        r3 = __hmax2(__hmul2(__hadd2(*(__half2*)&ra1.w, *(__half2*)&rb1.w), zh), hzero);
        v.x = *(uint32_t*)&r0; v.y = *(uint32_t*)&r1;
        v.z = *(uint32_t*)&r2; v.w = *(uint32_t*)&r3;
        *(uint4*)(dsm + aoff[bi] + a_sub_off + a_sw1) = v;
    };
    auto loadA = [&](int chunk) {
        const int kc = chunk * ECH;
        ra0 = *(const uint4*)(pd + kc + acol0);
        ra1 = *(const uint4*)(pd + kc + acol0 + 8);
        rb0 = *(const uint4*)(ps + kc + acol0);
        rb1 = *(const uint4*)(ps + kc + acol0 + 8);
    };
    auto issueB = [&](int chunk, int bi) {
        const char* gB = (const char*)(g_W2h + (size_t)chunk * (EN * ECH));
#pragma unroll
        for (int i = 0; i < 4; i++) {
            int j = (tid + i * 512) * 16;
            cpasync16(smem_base + boff[bi] + (uint32_t)j, gB + j);
        }
        CP_COMMIT();
    };

    loadA(0);
    issueB(0, 0);
    convStoreA(0, 0);
    CP_WAIT0();
    __syncthreads();

    for (int chunk = 0; chunk < NCHUNK; chunk++) {
        const int cur = chunk & 1;
        const int nxt = cur ^ 1;

        if (chunk < NCHUNK - 1) {
            loadA(chunk + 1);
            issueB(chunk + 1, nxt);
        }

#pragma unroll
        for (int ks = 0; ks < 4; ks++) {
            uint32_t a[4][4];
#pragma unroll
            for (int mi = 0; mi < 4; mi++) {
                uint32_t row = (uint32_t)(mi * 16 + a_r);
                ldm4(a[mi], smem_base + aoff[cur] + (uint32_t)(wsub * 8192)
                     + SWZ128(row * 128 + (uint32_t)(ks * 32) + a_kb));
            }
#pragma unroll
            for (int nig = 0; nig < 2; nig++) {
                uint32_t rr[4];
                uint32_t nrow = (uint32_t)(n0w + nig * 16 + b4_row);
                ldm4(rr, smem_base + boff[cur] + SWZ128(nrow * 128 + (uint32_t)(ks * 32) + b4_kb));
#pragma unroll
                for (int mi = 0; mi < 4; mi++) {
                    mma_f16(c[mi][2 * nig], a[mi], &rr[0]);
                    mma_f16(c[mi][2 * nig + 1], a[mi], &rr[2]);
                }
            }
        }

        if (chunk < NCHUNK - 1) {
            convStoreA(chunk + 1, nxt);
            CP_WAIT0();
        }
        __syncthreads();
    }

    // ---- epilogue: per sub-tile, fragments -> scratch -> segmented reduce ----
    float* tile = (float*)dsm;   // 64 x 258 fp32 = 66KB (reuses staging region)
    for (int s = 0; s < 2; s++) {
        if (wsub == s) {
#pragma unroll
            for (int mi = 0; mi < 4; mi++) {
                int r0 = mi * 16 + (lane >> 2);
                int r1 = r0 + 8;
#pragma unroll
                for (int ni = 0; ni < 4; ni++) {
                    int col = n0w + ni * 8 + 2 * (lane & 3);
                    float* cc = c[mi][ni];
                    *(float2*)&tile[r0 * TSTRIDE + col] = make_float2(cc[0], cc[1]);
                    *(float2*)&tile[r1 * TSTRIDE + col] = make_float2(cc[2], cc[3]);
                }
            }
        }
        __syncthreads();
        {
            const int col = tid & 255;
            const int rbeg = (tid >> 8) * 32;
            const int* sd = sdst + s * 64;
            float acc = 0.f;
            int curn = sd[rbeg];
#pragma unroll 4
            for (int r = rbeg; r < rbeg + 32; r++) {
                int d = sd[r];
                float v = tile[r * TSTRIDE + col];
                if (d != curn) {
                    atomicAdd(g_macc + (size_t)curn * MST + col, acc);
                    acc = 0.f;
                    curn = d;
                }
                acc += v;
            }
            atomicAdd(g_macc + (size_t)curn * MST + col, acc);
        }
        __syncthreads();
    }
}

// ---------------- launch ----------------
extern "C" void kernel_launch(void* const* d_in, const int* in_sizes, int n_in,
                              void* d_out, int out_size)
{
    const float* x   = (const float*)d_in[0];
    const void*  ei  = d_in[1];
    const float* z   = (const float*)d_in[2];
    const float* Wf  = (const float*)d_in[3];
    const float* bf  = (const float*)d_in[4];
    const float* W1  = (const float*)d_in[5];
    const float* b1  = (const float*)d_in[6];
    const float* W2  = (const float*)d_in[7];
    const float* b2  = (const float*)d_in[8];
    const float* Wih = (const float*)d_in[9];
    const float* bih = (const float*)d_in[10];
    const float* Whh = (const float*)d_in[11];
    const float* bhh = (const float*)d_in[12];
    const float* Wo  = (const float*)d_in[13];
    const float* bo  = (const float*)d_in[14];
    float* out = (float*)d_out;

    float *p_h, *p_macc, *p_W1ab, *p_biasab, *p_ic;
    float *p_WfXF, *p_biasWfX, *p_WhxF, *p_biasWhx;
    __half *p_fh16, *p_AB16, *p_WfX16, *p_W1ab16, *p_Whx16;
    cudaGetSymbolAddress((void**)&p_h, g_h);
    cudaGetSymbolAddress((void**)&p_macc, g_macc);
    cudaGetSymbolAddress((void**)&p_W1ab, g_W1ab);
    cudaGetSymbolAddress((void**)&p_biasab, g_biasab);
    cudaGetSymbolAddress((void**)&p_ic, g_invcnt);
    cudaGetSymbolAddress((void**)&p_WfXF, g_WfXF);
    cudaGetSymbolAddress((void**)&p_biasWfX, g_biasWfX);
    cudaGetSymbolAddress((void**)&p_WhxF, g_WhxF);
    cudaGetSymbolAddress((void**)&p_biasWhx, g_biasWhx);
    cudaGetSymbolAddress((void**)&p_fh16, g_fh16);
    cudaGetSymbolAddress((void**)&p_AB16, g_AB16);
    cudaGetSymbolAddress((void**)&p_WfX16, g_WfX16);
    cudaGetSymbolAddress((void**)&p_W1ab16, g_W1ab16);
    cudaGetSymbolAddress((void**)&p_Whx16, g_Whx16);

    static int smem_set = 0;
    if (!smem_set) {
        cudaFuncSetAttribute(k_edge_mma, cudaFuncAttributeMaxDynamicSharedMemorySize,
                             SM_EDGE_TOTAL);
        cudaFuncSetAttribute(k_gemm16, cudaFuncAttributeMaxDynamicSharedMemorySize,
                             SM_GEMM_TOTAL);
        smem_set = 1;
    }

    k_init<<<512, 256>>>();
    k_detect<<<512, 256>>>((const int*)ei);
    k_extract<<<(Ee + 255) / 256, 256>>>(ei);
    k_hist<<<(Ee + 255) / 256, 256>>>();
    k_cnt<<<(Nn + 255) / 256, 256>>>();
    k_scan<<<1, 512>>>();
    k_place<<<(Ee + 255) / 256, 256>>>(z);
    k_b2base<<<(Nn * MST + 255) / 256, 256>>>(b2);
    k_pack_w1<<<(192 * 1536 + 255) / 256, 256>>>(W1, b1);
    k_build_wfx<<<(256 * 256 + 255) / 256, 256>>>(Wf, Wo, bf, bo);
    k_build_whx<<<(320 * 1024 + 255) / 256, 256>>>(Whh, Wih, bhh, bih);
    k_pack_w2<<<(NCHUNK * EN * ECH + 255) / 256, 256>>>(W2);
    k_pack_b16<<<(256 * 256 + 255) / 256, 256>>>(p_WfXF, p_WfX16, 256, 256);
    k_pack_b16<<<(192 * 1536 + 255) / 256, 256>>>(p_W1ab, p_W1ab16, 192, 1536);
    k_pack_b16<<<(320 * 1024 + 255) / 256, 256>>>(p_WhxF, p_Whx16, 320, 1024);

    dim3 gfh((Nn + 127) / 128, 4);
    dim3 gab((Nn + 127) / 128, 24);
    dim3 ggh((Nn + 127) / 128, 16);
    int  gedge = Ee / EM;                 // 1250

    for (int t = 0; t < Tt; t++) {
        k_gemm16<<<gfh, 256, SM_GEMM_TOTAL>>>(p_h, p_WfX16, p_biasWfX, p_fh16,
                               Nn, 256, 256, nullptr, 1, 0, 1, 192, t, x, out);
        k_gemm16<<<gab, 256, SM_GEMM_TOTAL>>>(p_fh16, p_W1ab16, p_biasab, p_AB16,
                               Nn, 192, 1536, nullptr, 0, 1, 0, 1536, 0, nullptr, nullptr);
        k_edge_mma<<<gedge, 512, SM_EDGE_TOTAL>>>();
        k_gemm16<<<ggh, 256, SM_GEMM_TOTAL>>>(p_macc, p_Whx16, p_biasWhx, nullptr,
                               Nn, 320, 1024, p_ic, 0, 0, 2, 0, 0, nullptr, nullptr);
    }
    k_gemm16<<<gfh, 256, SM_GEMM_TOTAL>>>(p_h, p_WfX16, p_biasWfX, p_fh16,
                           Nn, 256, 256, nullptr, 1, 0, 1, 192, Tt, x, out);
}

// round 12
// speedup vs baseline: 1.1517x; 1.1517x over previous
#include <cuda_runtime.h>
#include <cuda_fp16.h>
#include <cstdint>

// ---------------- problem constants ----------------
#define Nn 10000
#define Ee 160000
#define Tt 32
#define Hh 256
#define NFd 192
#define TTEACH 24
#define MST 320            // macc row stride (256 msg + 6 inputs + pad)

// edge-GEMM tiling (R10 shape: 64 edges/CTA, 2 CTAs/SM)
#define EM 64
#define EN 256
#define EK 768
#define ECH 64
#define NCHUNK (EK/ECH)

#define SM_A0 0
#define SM_A1 8192
#define SM_B0 16384
#define SM_B1 49152
#define SM_EDGE_TOTAL 81920
#define TSTRIDE 258

// node GEMM smem
#define GM_A0 0
#define GM_A1 16384
#define GM_B0 32768
#define GM_B1 40960
#define SM_GEMM_TOTAL 49152

// ---------------- device scratch ----------------
static __device__ float  g_h[Nn * Hh];
static __device__ __half g_fh16[Nn * NFd];
static __device__ __half g_AB16[Nn * 1536];
static __device__ float  g_macc[Nn * MST];
static __device__ float  g_mbase[Nn * Hh];
static __device__ float  g_invcnt[Nn];
static __device__ float  g_cntf[Nn];
static __device__ float  g_zsum[Nn * 3];
static __device__ float  g_in6[Nn * 6];
static __device__ int    g_deg[Nn];
static __device__ int    g_base[Nn + 1];
static __device__ int    g_cur[Nn];
static __device__ int    g_src[Ee];
static __device__ int    g_dst[Ee];
static __device__ int    g_srcs[Ee];
static __device__ int    g_dsts[Ee];
static __device__ float  g_zs[3 * Ee];
static __device__ int    g_is32;
// weight staging + fp16 packs
static __device__ float  g_W1ab[192 * 1536];
static __device__ float  g_biasab[1536];
static __device__ float  g_WfXF[256 * 256];
static __device__ float  g_biasWfX[256];
static __device__ float  g_WhxF[320 * 1024];
static __device__ float  g_biasWhx[1024];
static __device__ __half g_WfX16[256 * 256];
static __device__ __half g_W1ab16[192 * 1536];
static __device__ __half g_Whx16[320 * 1024];
static __device__ __half g_W2h[NCHUNK * EN * ECH];

// ---------------- helpers ----------------
__device__ __forceinline__ uint32_t smem_u32(const void* p) {
    uint32_t a;
    asm("{ .reg .u64 t; cvta.to.shared.u64 t, %1; cvt.u32.u64 %0, t; }" : "=r"(a) : "l"(p));
    return a;
}
#define SWZ128(off) ((off) ^ (((off) >> 3) & 0x70))

__device__ __forceinline__ void ldm4(uint32_t* r, uint32_t addr) {
    asm volatile("ldmatrix.sync.aligned.m8n8.x4.shared.b16 {%0,%1,%2,%3}, [%4];"
                 : "=r"(r[0]), "=r"(r[1]), "=r"(r[2]), "=r"(r[3]) : "r"(addr));
}
__device__ __forceinline__ void ldm2(uint32_t* r, uint32_t addr) {
    asm volatile("ldmatrix.sync.aligned.m8n8.x2.shared.b16 {%0,%1}, [%2];"
                 : "=r"(r[0]), "=r"(r[1]) : "r"(addr));
}
__device__ __forceinline__ void mma_f16(float* c, const uint32_t* a, const uint32_t* b) {
    asm volatile(
        "mma.sync.aligned.m16n8k16.row.col.f32.f16.f16.f32 "
        "{%0,%1,%2,%3}, {%4,%5,%6,%7}, {%8,%9}, {%0,%1,%2,%3};"
        : "+f"(c[0]), "+f"(c[1]), "+f"(c[2]), "+f"(c[3])
        : "r"(a[0]), "r"(a[1]), "r"(a[2]), "r"(a[3]), "r"(b[0]), "r"(b[1]));
}
__device__ __forceinline__ void cpasync16(uint32_t smem_addr, const void* gptr) {
    asm volatile("cp.async.cg.shared.global [%0], [%1], 16;"
                 :: "r"(smem_addr), "l"(gptr) : "memory");
}
#define CP_COMMIT() asm volatile("cp.async.commit_group;" ::: "memory")
#define CP_WAIT0()  asm volatile("cp.async.wait_group 0;" ::: "memory")
// PDL: wait for stream-predecessor's writes to be visible
__device__ __forceinline__ void pdl_wait() {
    asm volatile("griddepcontrol.wait;" ::: "memory");
}

// ---------------- setup kernels ----------------
__global__ void k_init() {
    int i = blockIdx.x * blockDim.x + threadIdx.x;
    int st = gridDim.x * blockDim.x;
    for (int j = i; j < Nn * Hh; j += st) g_h[j] = 0.f;
    for (int j = i; j < Nn * 6; j += st) g_in6[j] = 0.f;
    for (int j = i; j < Nn; j += st) g_deg[j] = 0;
    for (int j = i; j < Nn * 3; j += st) g_zsum[j] = 0.f;
    if (i == 0) g_is32 = 0;
}

__global__ void k_detect(const int* __restrict__ w) {
    int i = blockIdx.x * blockDim.x + threadIdx.x;
    int st = gridDim.x * blockDim.x;
    for (int j = i; j < 2 * Ee; j += st) {
        if ((j & 1) && w[j] != 0) g_is32 = 1;
    }
}

__global__ void k_extract(const void* __restrict__ eiraw) {
    int e = blockIdx.x * blockDim.x + threadIdx.x;
    if (e >= Ee) return;
    if (g_is32) {
        const int* p = (const int*)eiraw;
        g_src[e] = p[e];
        g_dst[e] = p[Ee + e];
    } else {
        const long long* p = (const long long*)eiraw;
        g_src[e] = (int)p[e];
        g_dst[e] = (int)p[Ee + e];
    }
}

__global__ void k_hist() {
    int e = blockIdx.x * blockDim.x + threadIdx.x;
    if (e < Ee) atomicAdd(&g_deg[g_dst[e]], 1);
}

__global__ void k_cnt() {
    int n = blockIdx.x * blockDim.x + threadIdx.x;
    if (n < Nn) {
        float c = fmaxf((float)g_deg[n], 1.f);
        g_cntf[n] = c;
        g_invcnt[n] = 1.f / c;
    }
}

__global__ void k_scan() {
    __shared__ int part[512];
    const int tid = threadIdx.x;
    const int per = (Nn + 511) / 512;
    int start = tid * per;
    int s = 0;
    for (int j = 0; j < per; j++) {
        int idx = start + j;
        if (idx < Nn) s += g_deg[idx];
    }
    part[tid] = s;
    __syncthreads();
    if (tid == 0) {
        int acc = 0;
        for (int i = 0; i < 512; i++) { int v = part[i]; part[i] = acc; acc += v; }
    }
    __syncthreads();
    int acc = part[tid];
    for (int j = 0; j < per; j++) {
        int idx = start + j;
        if (idx < Nn) { g_base[idx] = acc; g_cur[idx] = acc; acc += g_deg[idx]; }
    }
    if (tid == 511) g_base[Nn] = acc;
}

__global__ void k_place(const float* __restrict__ z) {
    int e = blockIdx.x * blockDim.x + threadIdx.x;
    if (e >= Ee) return;
    int d = g_dst[e];
    int pos = atomicAdd(&g_cur[d], 1);
    g_srcs[pos] = g_src[e];
    g_dsts[pos] = d;
    float z1 = z[(size_t)e * 4 + 1];
    float z2 = z[(size_t)e * 4 + 2];
    float z3 = z[(size_t)e * 4 + 3];
    g_zs[pos] = z1;
    g_zs[Ee + pos] = z2;
    g_zs[2 * Ee + pos] = z3;
    atomicAdd(&g_zsum[d * 3 + 0], z1);
    atomicAdd(&g_zsum[d * 3 + 1], z2);
    atomicAdd(&g_zsum[d * 3 + 2], z3);
}

__global__ void k_b2base(const float* __restrict__ b2) {
    int idx = blockIdx.x * blockDim.x + threadIdx.x;
    if (idx >= Nn * MST) return;
    int n = idx / MST, c = idx % MST;
    if (c < 256) {
        float v = g_zsum[n * 3 + 0] * b2[c]
                + g_zsum[n * 3 + 1] * b2[256 + c]
                + g_zsum[n * 3 + 2] * b2[512 + c];
        g_mbase[n * 256 + c] = v;
        g_macc[idx] = v;
    } else {
        g_macc[idx] = 0.f;
    }
}

__global__ void k_pack_w1(const float* __restrict__ W1, const float* __restrict__ b1) {
    int idx = blockIdx.x * blockDim.x + threadIdx.x;
    if (idx < 192 * 1536) {
        int row = idx / 1536, c = idx % 1536;
        float v;
        if (c < 768) {
            int k = c >> 8, j = c & 255;
            v = W1[k * 98304 + row * 256 + j];
        } else {
            int c2 = c - 768;
            int k = c2 >> 8, j = c2 & 255;
            v = W1[k * 98304 + (row + 192) * 256 + j];
        }
        g_W1ab[idx] = v;
    }
    if (idx < 1536) g_biasab[idx] = (idx < 768) ? b1[idx] : 0.f;
}

__global__ void k_build_wfx(const float* __restrict__ Wf, const float* __restrict__ Wo,
                            const float* __restrict__ bf, const float* __restrict__ bo) {
    int idx = blockIdx.x * blockDim.x + threadIdx.x;
    if (idx >= 256 * 256) return;
    int k = idx >> 8, n = idx & 255;
    float v = 0.f;
    if (n < 192) v = Wf[k * 192 + n];
    else if (n < 198) v = Wo[k * 6 + (n - 192)];
    g_WfXF[idx] = v;
    if (idx < 256) {
        float b = 0.f;
        if (idx < 192) b = bf[idx];
        else if (idx < 198) b = bo[idx - 192];
        g_biasWfX[idx] = b;
    }
}

__global__ void k_build_whx(const float* __restrict__ Whh, const float* __restrict__ Wih,
                            const float* __restrict__ bhh, const float* __restrict__ bih) {
    int idx = blockIdx.x * blockDim.x + threadIdx.x;
    if (idx >= 320 * 1024) return;
    int k = idx >> 10, j = idx & 1023;
    int g = j >> 6, rem = j & 63, gate = rem >> 4;
    int ii = (g << 4) + (rem & 15);
    float v = 0.f;
    if (k < 256) {
        if (gate == 0) v = Whh[ii * 256 + k];
        else if (gate == 1) v = Whh[(256 + ii) * 256 + k];
        else if (gate == 2) v = Whh[(512 + ii) * 256 + k];
    } else if (k < 262) {
        int q = k - 256;
        if (gate == 0) v = Wih[ii * 6 + q];
        else if (gate == 1) v = Wih[(256 + ii) * 6 + q];
        else if (gate == 3) v = Wih[(512 + ii) * 6 + q];
    }
    g_WhxF[idx] = v;
    if (idx < 1024) {
        int gg = idx >> 6, rr = idx & 63, gt = rr >> 4;
        int i2 = (gg << 4) + (rr & 15);
        float b;
        if (gt == 0) b = bhh[i2] + bih[i2];
        else if (gt == 1) b = bhh[256 + i2] + bih[256 + i2];
        else if (gt == 2) b = bhh[512 + i2];
        else b = bih[512 + i2];
        g_biasWhx[idx] = b;
    }
}

__global__ void k_pack_b16(const float* __restrict__ src, __half* __restrict__ dst,
                           int Kd, int Nd) {
    int idx = blockIdx.x * blockDim.x + threadIdx.x;
    if (idx >= Kd * Nd) return;
    int k = idx / Nd, n = idx % Nd;
    int kc = k >> 6, kk = k & 63, nb = n >> 6, nn = n & 63;
    int tile = kc * (Nd >> 6) + nb;
    uint32_t off = SWZ128((uint32_t)(nn * 128 + kk * 2));
    dst[(size_t)tile * 4096 + off / 2] = __float2half_rn(src[idx]);
}

__global__ void k_pack_w2(const float* __restrict__ W2) {
    int idx = blockIdx.x * blockDim.x + threadIdx.x;
    if (idx >= NCHUNK * EN * ECH) return;
    int chunk = idx / (EN * ECH);
    int rem = idx % (EN * ECH);
    int n = rem / ECH, k = rem % ECH;
    float w = W2[(size_t)(chunk * ECH + k) * 256 + n];
    uint32_t off = SWZ128((uint32_t)(n * 128 + k * 2));
    g_W2h[(size_t)chunk * (EN * ECH) + off / 2] = __float2half_rn(w);
}

// ---------------- unified fp16 tensor-core GEMM (pipelined, fused epilogues) ----
// mode 0: plain fp16 C;  mode 1: fh fused (mu + input staging + macc reset);
// mode 2: gh fused (GRU gates -> g_h).  nblk_base offsets blockIdx.y.
__global__ void __launch_bounds__(256) k_gemm16(
    const void* __restrict__ A, const __half* __restrict__ Bpk,
    const float* __restrict__ bias, void* __restrict__ C,
    int M, int Kd, int Nd, const float* __restrict__ rowscale,
    int relu, int a_fp16, int mode, int c_stride,
    int t, const float* __restrict__ x, float* __restrict__ out, int nblk_base)
{
    extern __shared__ char gsm[];
    const uint32_t smem_base = smem_u32(gsm);

    const int tid = threadIdx.x;
    const int wid = tid >> 5;
    const int lane = tid & 31;
    const int m0 = blockIdx.x * 128;
    const int nblk = blockIdx.y + nblk_base;
    const int n0 = nblk * 64;
    const int nblocks = Nd >> 6;
    const int niter = Kd >> 6;

    const int m0w = (wid >> 1) * 32;
    const int n0w = (wid & 1) * 32;

    float c[2][4][4];
#pragma unroll
    for (int mi = 0; mi < 2; mi++)
#pragma unroll
        for (int ni = 0; ni < 4; ni++)
#pragma unroll
            for (int r = 0; r < 4; r++) c[mi][ni][r] = 0.f;

    const int arow = tid >> 1;
    const int acol0 = (tid & 1) * 32;
    const int am = m0 + arow;
    const bool av = am < M;
    const uint32_t a_sw[4] = {
        SWZ128((uint32_t)(arow * 128 + acol0 * 2)),
        SWZ128((uint32_t)(arow * 128 + (acol0 + 8) * 2)),
        SWZ128((uint32_t)(arow * 128 + (acol0 + 16) * 2)),
        SWZ128((uint32_t)(arow * 128 + (acol0 + 24) * 2))
    };

    const int a_r = lane & 15;
    const uint32_t a_kb = (uint32_t)((lane >> 4) << 4);
    const int b_r = lane & 7;
    const uint32_t b_kb = (uint32_t)(((lane >> 3) & 1) << 4);

    const uint32_t aoff[2] = {GM_A0, GM_A1};
    const uint32_t boff[2] = {GM_B0, GM_B1};

    auto issueB = [&](int kt, int bi) {
        const char* gB = (const char*)(Bpk + (size_t)((kt >> 6) * nblocks + nblk) * 4096);
        int j0 = tid * 16;
        cpasync16(smem_base + boff[bi] + (uint32_t)j0, gB + j0);
        cpasync16(smem_base + boff[bi] + (uint32_t)(j0 + 4096), gB + j0 + 4096);
        CP_COMMIT();
    };

    // PDL: B is static weights -> prefetch under predecessor's tail,
    // then wait before reading dependent A.
    issueB(0, 0);
    pdl_wait();

    float rs = 1.f;
    if (rowscale && av) rs = rowscale[am];

    auto stageA = [&](int kt, int bi) {
        if (a_fp16) {
            const __half* Ah = (const __half*)A + (size_t)am * Kd + kt;
#pragma unroll
            for (int i = 0; i < 4; i++) {
                uint4 v = make_uint4(0u, 0u, 0u, 0u);
                if (av) v = *(const uint4*)(Ah + acol0 + i * 8);
                *(uint4*)(gsm + aoff[bi] + a_sw[i]) = v;
            }
        } else {
            const float* Af = (const float*)A + (size_t)am * Kd + kt;
#pragma unroll
            for (int i = 0; i < 4; i++) {
                uint4 v = make_uint4(0u, 0u, 0u, 0u);
                if (av) {
                    float4 f0 = *(const float4*)(Af + acol0 + i * 8);
                    float4 f1 = *(const float4*)(Af + acol0 + i * 8 + 4);
                    __half2 h0 = __floats2half2_rn(f0.x * rs, f0.y * rs);
                    __half2 h1 = __floats2half2_rn(f0.z * rs, f0.w * rs);
                    __half2 h2 = __floats2half2_rn(f1.x * rs, f1.y * rs);
                    __half2 h3 = __floats2half2_rn(f1.z * rs, f1.w * rs);
                    v.x = *(uint32_t*)&h0; v.y = *(uint32_t*)&h1;
                    v.z = *(uint32_t*)&h2; v.w = *(uint32_t*)&h3;
                }
                *(uint4*)(gsm + aoff[bi] + a_sw[i]) = v;
            }
        }
    };

    stageA(0, 0);
    CP_WAIT0();
    __syncthreads();

    for (int it = 0; it < niter; it++) {
        const int cur = it & 1;
        const int nxt = cur ^ 1;
        if (it + 1 < niter) issueB((it + 1) << 6, nxt);

#pragma unroll
        for (int ks = 0; ks < 4; ks++) {
            uint32_t a[2][4];
#pragma unroll
            for (int mi = 0; mi < 2; mi++) {
                uint32_t row = (uint32_t)(m0w + mi * 16 + a_r);
                ldm4(a[mi], smem_base + aoff[cur] + SWZ128(row * 128 + (uint32_t)(ks * 32) + a_kb));
            }
#pragma unroll
            for (int ni = 0; ni < 4; ni++) {
                uint32_t nrow = (uint32_t)(n0w + ni * 8 + b_r);
                uint32_t b[2];
                ldm2(b, smem_base + boff[cur] + SWZ128(nrow * 128 + (uint32_t)(ks * 32) + b_kb));
                mma_f16(c[0][ni], a[0], b);
                mma_f16(c[1][ni], a[1], b);
            }
        }

        if (it + 1 < niter) {
            stageA((it + 1) << 6, nxt);
            CP_WAIT0();
        }
        __syncthreads();
    }

    if (mode == 2) {
        float* tile = (float*)gsm;   // 128 x 68
#pragma unroll
        for (int mi = 0; mi < 2; mi++) {
            int lr0 = m0w + mi * 16 + (lane >> 2);
            int lr1 = lr0 + 8;
#pragma unroll
            for (int ni = 0; ni < 4; ni++) {
                int col = n0w + ni * 8 + 2 * (lane & 3);
                float bv0 = bias[n0 + col], bv1 = bias[n0 + col + 1];
                float* cc = c[mi][ni];
                tile[lr0 * 68 + col] = cc[0] + bv0;
                tile[lr0 * 68 + col + 1] = cc[1] + bv1;
                tile[lr1 * 68 + col] = cc[2] + bv0;
                tile[lr1 * 68 + col + 1] = cc[3] + bv1;
            }
        }
        __syncthreads();
#pragma unroll
        for (int u = 0; u < 8; u++) {
            int unit = tid + u * 256;
            int row = unit >> 4, iloc = unit & 15;
            int gn = m0 + row;
            if (gn < M) {
                float gr  = tile[row * 68 + iloc];
                float gz  = tile[row * 68 + 16 + iloc];
                float gnh = tile[row * 68 + 32 + iloc];
                float gnx = tile[row * 68 + 48 + iloc];
                int hcol = nblk * 16 + iloc;
                float ic = rowscale[gn];
                float m = g_macc[(size_t)gn * MST + hcol] * ic;
                float r  = 1.f / (1.f + __expf(-gr));
                float zg = 1.f / (1.f + __expf(-gz));
                float arg = gnx + r * gnh;
                float nn = 1.f - 2.f / (__expf(2.f * arg) + 1.f);
                g_h[(size_t)gn * 256 + hcol] = (1.f - zg) * nn + zg * m;
            }
        }
        return;
    }

#pragma unroll
    for (int mi = 0; mi < 2; mi++) {
        int r0 = m0 + m0w + mi * 16 + (lane >> 2);
        int r1 = r0 + 8;
#pragma unroll
        for (int ni = 0; ni < 4; ni++) {
            int col = n0 + n0w + ni * 8 + 2 * (lane & 3);
            float bv0 = bias[col], bv1 = bias[col + 1];
            float* cc = c[mi][ni];
            float o00 = cc[0] + bv0, o01 = cc[1] + bv1;
            float o10 = cc[2] + bv0, o11 = cc[3] + bv1;
            if (relu) {
                o00 = fmaxf(o00, 0.f); o01 = fmaxf(o01, 0.f);
                o10 = fmaxf(o10, 0.f); o11 = fmaxf(o11, 0.f);
            }
            if (mode == 1) {
                if (r0 < M)
                    *(float2*)(g_macc + (size_t)r0 * MST + col) =
                        *(const float2*)(g_mbase + (size_t)r0 * 256 + col);
                if (r1 < M)
                    *(float2*)(g_macc + (size_t)r1 * MST + col) =
                        *(const float2*)(g_mbase + (size_t)r1 * 256 + col);
                if (col < 192) {
                    __half* Ch = (__half*)C;
                    if (r0 < M) {
                        __half2 h = __floats2half2_rn(o00, o01);
                        *(__half2*)(Ch + (size_t)r0 * c_stride + col) = h;
                    }
                    if (r1 < M) {
                        __half2 h = __floats2half2_rn(o10, o11);
                        *(__half2*)(Ch + (size_t)r1 * c_stride + col) = h;
                    }
                } else if (col < 198) {
                    int q = col - 192;
#pragma unroll
                    for (int half = 0; half < 2; half++) {
                        int rr = half ? r1 : r0;
                        float v0 = half ? o10 : o00;
                        float v1 = half ? o11 : o01;
                        if (rr < M) {
                            float mu0 = g_in6[rr * 6 + q] + v0;
                            float mu1 = g_in6[rr * 6 + q + 1] + v1;
                            if (t > 0) {
                                out[(size_t)rr * NFd + (t - 1) * 6 + q] = mu0;
                                out[(size_t)rr * NFd + (t - 1) * 6 + q + 1] = mu1;
                            }
                            float i0 = (t < TTEACH) ? x[(size_t)rr * NFd + t * 6 + q] : mu0;
                            float i1 = (t < TTEACH) ? x[(size_t)rr * NFd + t * 6 + q + 1] : mu1;
                            g_in6[rr * 6 + q] = i0;
                            g_in6[rr * 6 + q + 1] = i1;
                            float cf = g_cntf[rr];
                            g_macc[(size_t)rr * MST + 256 + q] = i0 * cf;
                            g_macc[(size_t)rr * MST + 256 + q + 1] = i1 * cf;
                        }
                    }
                }
            } else {
                __half* Ch = (__half*)C;
                if (r0 < M) {
                    __half2 h = __floats2half2_rn(o00, o01);
                    *(__half2*)(Ch + (size_t)r0 * c_stride + col) = h;
                }
                if (r1 < M) {
                    __half2 h = __floats2half2_rn(o10, o11);
                    *(__half2*)(Ch + (size_t)r1 * c_stride + col) = h;
                }
            }
        }
    }
}

// ---------------- edge GEMM: 64x256, 2 CTAs/SM, warp tile 64x32 (R10 shape) ----
__global__ void __launch_bounds__(256, 2)
k_edge_mma()
{
    extern __shared__ char dsm[];
    __shared__ int sdst[EM];
    __shared__ float sz[3][EM];

    const uint32_t smem_base = smem_u32(dsm);
    const int tid = threadIdx.x;
    const int wid = tid >> 5;
    const int lane = tid & 31;
    const int e0 = blockIdx.x * EM;

    if (tid < EM) {
        sdst[tid] = g_dsts[e0 + tid];
        sz[0][tid] = g_zs[e0 + tid];
        sz[1][tid] = g_zs[Ee + e0 + tid];
        sz[2][tid] = g_zs[2 * Ee + e0 + tid];
    }

    const int n0w = wid * 32;

    float c[4][4][4];
#pragma unroll
    for (int mi = 0; mi < 4; mi++)
#pragma unroll
        for (int ni = 0; ni < 4; ni++)
#pragma unroll
            for (int r = 0; r < 4; r++) c[mi][ni][r] = 0.f;

    const int arow = tid >> 2;
    const int acol0 = (tid & 3) * 16;
    const int drow = g_dsts[e0 + arow];
    const int srow = g_srcs[e0 + arow];
    const __half* pd = g_AB16 + (size_t)drow * 1536;
    const __half* ps = g_AB16 + (size_t)srow * 1536 + 768;
    const uint32_t a_sw0 = SWZ128((uint32_t)(arow * 128 + acol0 * 2));
    const uint32_t a_sw1 = SWZ128((uint32_t)(arow * 128 + (acol0 + 8) * 2));

    const int a_r = lane & 15;
    const uint32_t a_kb = (uint32_t)((lane >> 4) << 4);
    const int b4_row = (lane & 7) + ((lane >> 4) << 3);
    const uint32_t b4_kb = (uint32_t)(((lane >> 3) & 1) << 4);

    const __half2 hzero = __float2half2_rn(0.f);
    const uint32_t aoff[2] = {SM_A0, SM_A1};
    const uint32_t boff[2] = {SM_B0, SM_B1};

    uint4 ra0, ra1, rb0, rb1;

    auto issueB = [&](int chunk, int bi) {
        const char* gB = (const char*)(g_W2h + (size_t)chunk * (EN * ECH));
#pragma unroll
        for (int i = 0; i < 8; i++) {
            int j = (tid + i * 256) * 16;
            cpasync16(smem_base + boff[bi] + (uint32_t)j, gB + j);
        }
        CP_COMMIT();
    };
    auto loadA = [&](int chunk) {
        const int kc = chunk * ECH;
        ra0 = *(const uint4*)(pd + kc + acol0);
        ra1 = *(const uint4*)(pd + kc + acol0 + 8);
        rb0 = *(const uint4*)(ps + kc + acol0);
        rb1 = *(const uint4*)(ps + kc + acol0 + 8);
    };
    auto convStoreA = [&](int chunk, int bi) {
        __half2 zh = __float2half2_rn(sz[chunk >> 2][arow]);
        __half2 r0 = __hmax2(__hmul2(__hadd2(*(__half2*)&ra0.x, *(__half2*)&rb0.x), zh), hzero);
        __half2 r1 = __hmax2(__hmul2(__hadd2(*(__half2*)&ra0.y, *(__half2*)&rb0.y), zh), hzero);
        __half2 r2 = __hmax2(__hmul2(__hadd2(*(__half2*)&ra0.z, *(__half2*)&rb0.z), zh), hzero);
        __half2 r3 = __hmax2(__hmul2(__hadd2(*(__half2*)&ra0.w, *(__half2*)&rb0.w), zh), hzero);
        uint4 v;
        v.x = *(uint32_t*)&r0; v.y = *(uint32_t*)&r1;
        v.z = *(uint32_t*)&r2; v.w = *(uint32_t*)&r3;
        *(uint4*)(dsm + aoff[bi] + a_sw0) = v;
        r0 = __hmax2(__hmul2(__hadd2(*(__half2*)&ra1.x, *(__half2*)&rb1.x), zh), hzero);
        r1 = __hmax2(__hmul2(__hadd2(*(__half2*)&ra1.y, *(__half2*)&rb1.y), zh), hzero);
        r2 = __hmax2(__hmul2(__hadd2(*(__half2*)&ra1.z, *(__half2*)&rb1.z), zh), hzero);
        r3 = __hmax2(__hmul2(__hadd2(*(__half2*)&ra1.w, *(__half2*)&rb1.w), zh), hzero);
        v.x = *(uint32_t*)&r0; v.y = *(uint32_t*)&r1;
        v.z = *(uint32_t*)&r2; v.w = *(uint32_t*)&r3;
        *(uint4*)(dsm + aoff[bi] + a_sw1) = v;
    };

    // PDL: B weights are static -> prefetch under predecessor's tail;
    // wait before reading dependent g_AB16.
    issueB(0, 0);
    pdl_wait();
    loadA(0);
    convStoreA(0, 0);
    CP_WAIT0();
    __syncthreads();

    for (int chunk = 0; chunk < NCHUNK; chunk++) {
        const int cur = chunk & 1;
        const int nxt = cur ^ 1;

        if (chunk < NCHUNK - 1) {
            loadA(chunk + 1);
            issueB(chunk + 1, nxt);
        }

#pragma unroll
        for (int ks = 0; ks < 4; ks++) {
            uint32_t a[4][4];
#pragma unroll
            for (int mi = 0; mi < 4; mi++) {
                uint32_t row = (uint32_t)(mi * 16 + a_r);
                ldm4(a[mi], smem_base + aoff[cur] + SWZ128(row * 128 + (uint32_t)(ks * 32) + a_kb));
            }
#pragma unroll
            for (int nig = 0; nig < 2; nig++) {
                uint32_t rr[4];
                uint32_t nrow = (uint32_t)(n0w + nig * 16 + b4_row);
                ldm4(rr, smem_base + boff[cur] + SWZ128(nrow * 128 + (uint32_t)(ks * 32) + b4_kb));
#pragma unroll
                for (int mi = 0; mi < 4; mi++) {
                    mma_f16(c[mi][2 * nig], a[mi], &rr[0]);
                    mma_f16(c[mi][2 * nig + 1], a[mi], &rr[2]);
                }
            }
        }

        if (chunk < NCHUNK - 1) {
            convStoreA(chunk + 1, nxt);
            CP_WAIT0();
        }
        __syncthreads();
    }

    // ---- epilogue: fragments -> SMEM tile -> segmented reduce ----
    float* tile = (float*)dsm;
#pragma unroll
    for (int mi = 0; mi < 4; mi++) {
        int r0 = mi * 16 + (lane >> 2);
        int r1 = r0 + 8;
#pragma unroll
        for (int ni = 0; ni < 4; ni++) {
            int col = n0w + ni * 8 + 2 * (lane & 3);
            float* cc = c[mi][ni];
            *(float2*)&tile[r0 * TSTRIDE + col] = make_float2(cc[0], cc[1]);
            *(float2*)&tile[r1 * TSTRIDE + col] = make_float2(cc[2], cc[3]);
        }
    }
    __syncthreads();

    {
        const int col = tid;
        float acc = 0.f;
        int curn = sdst[0];
#pragma unroll 4
        for (int r = 0; r < EM; r++) {
            int d = sdst[r];
            float v = tile[r * TSTRIDE + col];
            if (d != curn) {
                atomicAdd(g_macc + (size_t)curn * MST + col, acc);
                acc = 0.f;
                curn = d;
            }
            acc += v;
        }
        atomicAdd(g_macc + (size_t)curn * MST + col, acc);
    }
}

// ---------------- launch ----------------
extern "C" void kernel_launch(void* const* d_in, const int* in_sizes, int n_in,
                              void* d_out, int out_size)
{
    const float* x   = (const float*)d_in[0];
    const void*  ei  = d_in[1];
    const float* z   = (const float*)d_in[2];
    const float* Wf  = (const float*)d_in[3];
    const float* bf  = (const float*)d_in[4];
    const float* W1  = (const float*)d_in[5];
    const float* b1  = (const float*)d_in[6];
    const float* W2  = (const float*)d_in[7];
    const float* b2  = (const float*)d_in[8];
    const float* Wih = (const float*)d_in[9];
    const float* bih = (const float*)d_in[10];
    const float* Whh = (const float*)d_in[11];
    const float* bhh = (const float*)d_in[12];
    const float* Wo  = (const float*)d_in[13];
    const float* bo  = (const float*)d_in[14];
    float* out = (float*)d_out;

    float *p_h, *p_macc, *p_W1ab, *p_biasab, *p_ic;
    float *p_WfXF, *p_biasWfX, *p_WhxF, *p_biasWhx;
    __half *p_fh16, *p_AB16, *p_WfX16, *p_W1ab16, *p_Whx16;
    cudaGetSymbolAddress((void**)&p_h, g_h);
    cudaGetSymbolAddress((void**)&p_macc, g_macc);
    cudaGetSymbolAddress((void**)&p_W1ab, g_W1ab);
    cudaGetSymbolAddress((void**)&p_biasab, g_biasab);
    cudaGetSymbolAddress((void**)&p_ic, g_invcnt);
    cudaGetSymbolAddress((void**)&p_WfXF, g_WfXF);
    cudaGetSymbolAddress((void**)&p_biasWfX, g_biasWfX);
    cudaGetSymbolAddress((void**)&p_WhxF, g_WhxF);
    cudaGetSymbolAddress((void**)&p_biasWhx, g_biasWhx);
    cudaGetSymbolAddress((void**)&p_fh16, g_fh16);
    cudaGetSymbolAddress((void**)&p_AB16, g_AB16);
    cudaGetSymbolAddress((void**)&p_WfX16, g_WfX16);
    cudaGetSymbolAddress((void**)&p_W1ab16, g_W1ab16);
    cudaGetSymbolAddress((void**)&p_Whx16, g_Whx16);

    static int smem_set = 0;
    if (!smem_set) {
        cudaFuncSetAttribute(k_edge_mma, cudaFuncAttributeMaxDynamicSharedMemorySize,
                             SM_EDGE_TOTAL);
        cudaFuncSetAttribute(k_gemm16, cudaFuncAttributeMaxDynamicSharedMemorySize,
                             SM_GEMM_TOTAL);
        smem_set = 1;
    }

    k_init<<<512, 256>>>();
    k_detect<<<512, 256>>>((const int*)ei);
    k_extract<<<(Ee + 255) / 256, 256>>>(ei);
    k_hist<<<(Ee + 255) / 256, 256>>>();
    k_cnt<<<(Nn + 255) / 256, 256>>>();
    k_scan<<<1, 512>>>();
    k_place<<<(Ee + 255) / 256, 256>>>(z);
    k_b2base<<<(Nn * MST + 255) / 256, 256>>>(b2);
    k_pack_w1<<<(192 * 1536 + 255) / 256, 256>>>(W1, b1);
    k_build_wfx<<<(256 * 256 + 255) / 256, 256>>>(Wf, Wo, bf, bo);
    k_build_whx<<<(320 * 1024 + 255) / 256, 256>>>(Whh, Wih, bhh, bih);
    k_pack_w2<<<(NCHUNK * EN * ECH + 255) / 256, 256>>>(W2);
    k_pack_b16<<<(256 * 256 + 255) / 256, 256>>>(p_WfXF, p_WfX16, 256, 256);
    k_pack_b16<<<(192 * 1536 + 255) / 256, 256>>>(p_W1ab, p_W1ab16, 192, 1536);
    k_pack_b16<<<(320 * 1024 + 255) / 256, 256>>>(p_WhxF, p_Whx16, 320, 1024);

    // PDL launch plumbing
    cudaLaunchAttribute pdlAttr;
    pdlAttr.id = cudaLaunchAttributeProgrammaticStreamSerialization;
    pdlAttr.val.programmaticStreamSerializationAllowed = 1;

    cudaLaunchConfig_t cfgGemm = {};
    cfgGemm.blockDim = {256, 1, 1};
    cfgGemm.dynamicSmemBytes = SM_GEMM_TOTAL;
    cfgGemm.stream = 0;
    cfgGemm.attrs = &pdlAttr;
    cfgGemm.numAttrs = 1;

    cudaLaunchConfig_t cfgEdge = {};
    cfgEdge.blockDim = {256, 1, 1};
    cfgEdge.gridDim = {(unsigned)(Ee / EM), 1, 1};   // 2500
    cfgEdge.dynamicSmemBytes = SM_EDGE_TOTAL;
    cfgEdge.stream = 0;
    cfgEdge.attrs = &pdlAttr;
    cfgEdge.numAttrs = 1;

    dim3 gfh(79, 4);
    dim3 gab(79, 24);
    dim3 ggh(79, 16);
    dim3 gfh_tail(79, 1);

    for (int t = 0; t < Tt; t++) {
        // fh fused: fh16 + mu(t-1) + inputs(t) staging + macc<-mbase reset
        cfgGemm.gridDim = gfh;
        cudaLaunchKernelEx(&cfgGemm, k_gemm16,
            (const void*)p_h, (const __half*)p_WfX16, (const float*)p_biasWfX, (void*)p_fh16,
            Nn, 256, 256, (const float*)nullptr, 1, 0, 1, 192, t, x, out, 0);
        // AB16 = fh16 @ W1ab
        cfgGemm.gridDim = gab;
        cudaLaunchKernelEx(&cfgGemm, k_gemm16,
            (const void*)p_fh16, (const __half*)p_W1ab16, (const float*)p_biasab, (void*)p_AB16,
            Nn, 192, 1536, (const float*)nullptr, 0, 1, 0, 1536, 0,
            (const float*)nullptr, (float*)nullptr, 0);
        // edge MLP2 + scatter (adds into macc)
        cudaLaunchKernelEx(&cfgEdge, k_edge_mma);
        // gh fused: [m|inputs] @ [Whh|Wih] -> GRU gates -> g_h
        cfgGemm.gridDim = ggh;
        cudaLaunchKernelEx(&cfgGemm, k_gemm16,
            (const void*)p_macc, (const __half*)p_Whx16, (const float*)p_biasWhx, (void*)nullptr,
            Nn, 320, 1024, (const float*)p_ic, 0, 0, 2, 0, 0,
            (const float*)nullptr, (float*)nullptr, 0);
    }
    // tail: emit mu(31) — only the mu N-block (nblk_base=3)
    cfgGemm.gridDim = gfh_tail;
    cudaLaunchKernelEx(&cfgGemm, k_gemm16,
        (const void*)p_h, (const __half*)p_WfX16, (const float*)p_biasWfX, (void*)p_fh16,
        Nn, 256, 256, (const float*)nullptr, 1, 0, 1, 192, Tt, x, out, 3);
}